// round 10
// baseline (speedup 1.0000x reference)
#include <cuda_runtime.h>
#include <cstdint>
#include <cstddef>

// BioConvolution: 256 independent GEMMs  C_l[64,128] = A_l[64,1024] * B_l[1024,128]
// Round 10: K-split x2 -> 512 CTAs (better SM balance + 3 CTAs/SM concurrency).
// Each CTA computes a K-half partial with the verified fp16 ldmatrix/mma
// pipeline (K-chunks of 32, 4-stage smem ring, deferred-cvt register buffer).
// Last-arriving CTA of each pair combines (partner partial + own regs + bias
// + relu) -- no inter-CTA waiting, deadlock-free, deterministic output.

namespace {

constexpr int NST = 16;            // K chunks of 32 per half (half = 512)
constexpr int AH  = 40;            // A smem stride halves (80B)
constexpr int BH  = 136;           // B smem stride halves (272B)
constexpr int TA_B  = 64 * AH * 2;            // 5120 B
constexpr int STG_B = TA_B + 32 * BH * 2;     // 13824 B
constexpr int SMEM_BYTES = 4 * STG_B;         // 55296 B -> 3 CTAs/SM

__device__ float g_part[2][256][8192];   // per-half partial tiles (16 MB)
__device__ int   g_cnt[256];

__device__ __forceinline__ uint32_t smem_u32(const void* p) {
    return static_cast<uint32_t>(__cvta_generic_to_shared(p));
}
__device__ __forceinline__ uint32_t pack_h2(float lo, float hi) {
    uint32_t d;
    asm("cvt.rn.f16x2.f32 %0, %1, %2;" : "=r"(d) : "f"(hi), "f"(lo));
    return d;
}
__device__ __forceinline__ void sts64(uint32_t a, uint32_t x, uint32_t y) {
    asm volatile("st.shared.v2.b32 [%0], {%1,%2};" :: "r"(a), "r"(x), "r"(y));
}
__device__ __forceinline__ void ldmx4(uint32_t* r, uint32_t a) {
    asm volatile("ldmatrix.sync.aligned.m8n8.x4.shared.b16 {%0,%1,%2,%3}, [%4];"
                 : "=r"(r[0]), "=r"(r[1]), "=r"(r[2]), "=r"(r[3]) : "r"(a));
}
__device__ __forceinline__ void ldmx4t(uint32_t* r, uint32_t a) {
    asm volatile("ldmatrix.sync.aligned.m8n8.x4.trans.shared.b16 {%0,%1,%2,%3}, [%4];"
                 : "=r"(r[0]), "=r"(r[1]), "=r"(r[2]), "=r"(r[3]) : "r"(a));
}
__device__ __forceinline__ void mma_f16(float* c, const uint32_t* a, const uint32_t* b) {
    asm volatile(
        "mma.sync.aligned.m16n8k16.row.col.f32.f16.f16.f32 "
        "{%0,%1,%2,%3}, {%4,%5,%6,%7}, {%8,%9}, {%0,%1,%2,%3};"
        : "+f"(c[0]), "+f"(c[1]), "+f"(c[2]), "+f"(c[3])
        : "r"(a[0]), "r"(a[1]), "r"(a[2]), "r"(a[3]), "r"(b[0]), "r"(b[1]));
}

__global__ void zero_cnt_kernel() { g_cnt[threadIdx.x] = 0; }

__global__ __launch_bounds__(256, 3)
void bioconv_ks_kernel(const float* __restrict__ X,
                       const float* __restrict__ filt,
                       const float* __restrict__ bias,
                       float* __restrict__ out) {
    extern __shared__ __align__(16) char smem[];
    const uint32_t sb = smem_u32(smem);
    __shared__ int s_role;

    const int tid  = threadIdx.x;
    const int l    = blockIdx.x >> 1;
    const int half = blockIdx.x & 1;
    const int r    = l >> 4;
    const int cc   = l & 15;

    // ---- coalesced loader mapping (K-chunk = 32 floats) ----
    const int ar = tid >> 3, ac = tid & 7;    // A f4: row v*32+ar? no: id scheme below
    const int br = tid >> 5, bc = tid & 31;   // B f4

    // A chunk: 64 rows x 8 f4; thread v-th: row = (v*256+tid)>>3 = v*32+ar, col ac
    const float* gA0 = X + (size_t)ar * 262144 + r * 16384 + cc * 256 + ac * 4;
    // B chunk: 32 rows x 32 f4; thread v-th: row = v*8+br, col bc
    const float* gB0 = filt + (size_t)l * 131072 + (size_t)(half * 512) * 128
                       + (size_t)br * 128 + bc * 4;

    const uint32_t a_sts = (uint32_t)(ar * AH + ac * 4) * 2;
    const uint32_t b_sts = (uint32_t)TA_B + (uint32_t)(br * BH + bc * 4) * 2;

    // ---- compute mapping: 8 warps, 2(M) x 4(N), warp tile 32x32 ----
    const int lane = tid & 31;
    const int wid  = tid >> 5;
    const int wm   = wid >> 2;
    const int wn   = wid & 3;
    const int g    = lane >> 2;
    const int t4   = lane & 3;

    const uint32_t a_off = (uint32_t)((wm * 32 + (lane & 15)) * 80 + (lane >> 4) * 16);
    const uint32_t b_off = (uint32_t)TA_B +
        (uint32_t)((lane & 15) * 272 + (wn * 32 + ((lane >> 4) & 1) * 8) * 2);

    float acc[2][4][4];
#pragma unroll
    for (int i = 0; i < 2; ++i)
#pragma unroll
        for (int j = 0; j < 4; ++j)
#pragma unroll
            for (int k = 0; k < 4; ++k) acc[i][j][k] = 0.f;

    float4 fb[6];  // 2 A-f4 + 4 B-f4

    auto ldg_chunk = [&](int t) {
        const int k0 = half * 512 + t * 32;
        const float* ga = gA0 + (k0 >> 8) * 4096 + ((k0 >> 6) & 3) * 64
                          + ((k0 >> 5) & 1) * 32;
#pragma unroll
        for (int v = 0; v < 2; ++v)
            fb[v] = *reinterpret_cast<const float4*>(ga + (size_t)v * 32 * 262144);
        const float* gb = gB0 + (size_t)t * 4096;
#pragma unroll
        for (int v = 0; v < 4; ++v)
            fb[2 + v] = *reinterpret_cast<const float4*>(gb + v * 1024);
    };
    auto cvt_sts = [&](int s) {
        const uint32_t base = sb + s * STG_B;
#pragma unroll
        for (int v = 0; v < 2; ++v)
            sts64(base + a_sts + v * 32 * (AH * 2),
                  pack_h2(fb[v].x, fb[v].y), pack_h2(fb[v].z, fb[v].w));
#pragma unroll
        for (int v = 0; v < 4; ++v)
            sts64(base + b_sts + v * 8 * (BH * 2),
                  pack_h2(fb[2 + v].x, fb[2 + v].y),
                  pack_h2(fb[2 + v].z, fb[2 + v].w));
    };

    ldg_chunk(0); cvt_sts(0);
    ldg_chunk(1); cvt_sts(1);
    ldg_chunk(2);

    for (int t = 0; t < NST; ++t) {
        __syncthreads();
        if (t + 2 < NST) cvt_sts((t + 2) & 3);
        if (t + 3 < NST) ldg_chunk(t + 3);

        const uint32_t base = sb + (t & 3) * STG_B;
        const uint32_t aa = base + a_off;
        const uint32_t bb = base + b_off;

#pragma unroll
        for (int kh = 0; kh < 2; ++kh) {
            uint32_t A0[4], A1[4], B0[4], B1[4];
            ldmx4(A0, aa + kh * 32);
            ldmx4(A1, aa + 16 * (AH * 2) + kh * 32);
            ldmx4t(B0, bb + kh * 16 * (BH * 2));
            ldmx4t(B1, bb + 32 + kh * 16 * (BH * 2));

            mma_f16(acc[0][0], A0, &B0[0]);
            mma_f16(acc[0][1], A0, &B0[2]);
            mma_f16(acc[0][2], A0, &B1[0]);
            mma_f16(acc[0][3], A0, &B1[2]);
            mma_f16(acc[1][0], A1, &B0[0]);
            mma_f16(acc[1][1], A1, &B0[2]);
            mma_f16(acc[1][2], A1, &B1[0]);
            mma_f16(acc[1][3], A1, &B1[2]);
        }
    }

    // ---------------- combine protocol (no waiting) ----------------
    // role 1: partner already done -> combine directly (skip own write)
    // else write own partial; atomicAdd; old==1 -> combine (role 2), else exit.
    if (tid == 0) {
        const int seen = *((volatile int*)&g_cnt[l]);
        s_role = (seen != 0) ? 1 : 0;
    }
    __syncthreads();
    int role = s_role;

    if (role == 0) {
        float* mp = &g_part[half][l][0];
#pragma unroll
        for (int nt = 0; nt < 4; ++nt) {
            const int n0 = wn * 32 + nt * 8 + t4 * 2;
#pragma unroll
            for (int mt = 0; mt < 2; ++mt) {
                const int m = wm * 32 + mt * 16 + g;
                *reinterpret_cast<float2*>(mp + m * 128 + n0) =
                    make_float2(acc[mt][nt][0], acc[mt][nt][1]);
                *reinterpret_cast<float2*>(mp + (m + 8) * 128 + n0) =
                    make_float2(acc[mt][nt][2], acc[mt][nt][3]);
            }
        }
        __threadfence();
        __syncthreads();
        if (tid == 0) {
            const int old = atomicAdd(&g_cnt[l], 1);
            s_role = (old == 1) ? 2 : 3;
        }
        __syncthreads();
        role = s_role;
        if (role == 3) return;  // partner will combine
    }

    // combine: read partner partial (+fence acquire), add own acc, bias, relu
    __threadfence();
    const float* pp = &g_part[half ^ 1][l][0];
#pragma unroll
    for (int nt = 0; nt < 4; ++nt) {
        const int n0 = wn * 32 + nt * 8 + t4 * 2;
        const float2 bv = *reinterpret_cast<const float2*>(bias + n0);
#pragma unroll
        for (int mt = 0; mt < 2; ++mt) {
            const int m = wm * 32 + mt * 16 + g;
            const float2 p0 = __ldcg(reinterpret_cast<const float2*>(pp + m * 128 + n0));
            const float2 p1 = __ldcg(reinterpret_cast<const float2*>(pp + (m + 8) * 128 + n0));
            float2 o0, o1;
            o0.x = fmaxf(acc[mt][nt][0] + p0.x + bv.x, 0.f);
            o0.y = fmaxf(acc[mt][nt][1] + p0.y + bv.y, 0.f);
            o1.x = fmaxf(acc[mt][nt][2] + p1.x + bv.x, 0.f);
            o1.y = fmaxf(acc[mt][nt][3] + p1.y + bv.y, 0.f);
            *reinterpret_cast<float2*>(out + ((size_t)m * 256 + l) * 128 + n0) = o0;
            *reinterpret_cast<float2*>(out + ((size_t)(m + 8) * 256 + l) * 128 + n0) = o1;
        }
    }
}

}  // namespace

extern "C" void kernel_launch(void* const* d_in, const int* in_sizes, int n_in,
                              void* d_out, int out_size) {
    const float* X    = (const float*)d_in[0];
    const float* filt = (const float*)d_in[1];
    const float* bias = (const float*)d_in[2];
    float* out        = (float*)d_out;

    zero_cnt_kernel<<<1, 256>>>();
    cudaFuncSetAttribute(bioconv_ks_kernel,
                         cudaFuncAttributeMaxDynamicSharedMemorySize, SMEM_BYTES);
    bioconv_ks_kernel<<<512, 256, SMEM_BYTES>>>(X, filt, bias, out);
}